// round 15
// baseline (speedup 1.0000x reference)
#include <cuda_runtime.h>
#include <cuda_bf16.h>
#include <cstdint>
#include <math.h>

#define B_SZ    2
#define L_SEQ   2048
#define D_MODEL 1024
#define D_INNER 2048
#define D_STATE 16
#define DT_RANK 64
#define NTOK    (B_SZ * L_SEQ)            /* 4096 tokens */
#define XPROJ   (DT_RANK + 2 * D_STATE)   /* 96 */

/* ================= scratch (no allocations allowed) ================= */
__device__ float g_xz[(size_t)NTOK * (2 * D_INNER)];
__device__ float g_xc[(size_t)NTOK * D_INNER];
__device__ float g_xp[(size_t)NTOK * XPROJ];
__device__ float g_xp_part[(size_t)4 * NTOK * XPROJ];
__device__ float g_dt[(size_t)NTOK * D_INNER];

__device__ __nv_bfloat16 g_x_hi [(size_t)NTOK * D_MODEL];
__device__ __nv_bfloat16 g_x_lo [(size_t)NTOK * D_MODEL];
__device__ __nv_bfloat16 g_wi_hi[(size_t)(2 * D_INNER) * D_MODEL];
__device__ __nv_bfloat16 g_wi_lo[(size_t)(2 * D_INNER) * D_MODEL];
__device__ __nv_bfloat16 g_wx_hi[(size_t)XPROJ * D_INNER];
__device__ __nv_bfloat16 g_wx_lo[(size_t)XPROJ * D_INNER];
__device__ __nv_bfloat16 g_wd_hi[(size_t)D_INNER * DT_RANK];
__device__ __nv_bfloat16 g_wd_lo[(size_t)D_INNER * DT_RANK];
__device__ __nv_bfloat16 g_wo_hi[(size_t)D_MODEL * D_INNER];
__device__ __nv_bfloat16 g_wo_lo[(size_t)D_MODEL * D_INNER];
__device__ __nv_bfloat16 g_xc_hi[(size_t)NTOK * D_INNER];
__device__ __nv_bfloat16 g_xc_lo[(size_t)NTOK * D_INNER];
__device__ __nv_bfloat16 g_xp_hi[(size_t)NTOK * XPROJ];
__device__ __nv_bfloat16 g_xp_lo[(size_t)NTOK * XPROJ];
__device__ __nv_bfloat16 g_y_hi [(size_t)NTOK * D_INNER];
__device__ __nv_bfloat16 g_y_lo [(size_t)NTOK * D_INNER];

__device__ __forceinline__ float softplusf(float x) {
    return fmaxf(x, 0.f) + log1pf(__expf(-fabsf(x)));
}
__device__ __forceinline__ uint32_t smem_u32(const void* p) {
    uint32_t a;
    asm("{ .reg .u64 t; cvta.to.shared.u64 t, %1; cvt.u32.u64 %0, t; }" : "=r"(a) : "l"(p));
    return a;
}
__device__ __forceinline__ void cp_async16(uint32_t dst, const void* src, int src_bytes) {
    asm volatile("cp.async.cg.shared.global [%0], [%1], 16, %2;"
                 :: "r"(dst), "l"(src), "r"(src_bytes) : "memory");
}
#define CP_COMMIT() asm volatile("cp.async.commit_group;" ::: "memory")
#define CP_WAIT0()  asm volatile("cp.async.wait_group 0;" ::: "memory")
#define LDSM_X4(d, a) \
    asm volatile("ldmatrix.sync.aligned.m8n8.x4.shared.b16 {%0,%1,%2,%3}, [%4];" \
                 : "=r"((d)[0]), "=r"((d)[1]), "=r"((d)[2]), "=r"((d)[3]) : "r"(a))
__device__ __forceinline__ void mma16816(float* c, const uint32_t* a, uint32_t b0, uint32_t b1) {
    asm volatile("mma.sync.aligned.m16n8k16.row.col.f32.bf16.bf16.f32 "
                 "{%0,%1,%2,%3}, {%4,%5,%6,%7}, {%8,%9}, {%0,%1,%2,%3};"
                 : "+f"(c[0]), "+f"(c[1]), "+f"(c[2]), "+f"(c[3])
                 : "r"(a[0]), "r"(a[1]), "r"(a[2]), "r"(a[3]), "r"(b0), "r"(b1));
}

/* ---------------- fp32 -> (hi, lo) bf16 split ---------------- */
__device__ __forceinline__ void split1(float v, __nv_bfloat16* hi, __nv_bfloat16* lo, size_t i) {
    __nv_bfloat16 h = __float2bfloat16(v);
    hi[i] = h;
    lo[i] = __float2bfloat16(v - __bfloat162float(h));
}

__global__ void cvt_pair(const float* __restrict__ s, __nv_bfloat16* __restrict__ hi,
                         __nv_bfloat16* __restrict__ lo, int n)
{
    int i = blockIdx.x * blockDim.x + threadIdx.x;
    if (i >= n) return;
    split1(s[i], hi, lo, i);
}

/* merged cvt for three arrays */
__global__ void cvt3(const float* __restrict__ a, __nv_bfloat16* ah, __nv_bfloat16* al, int na,
                     const float* __restrict__ b, __nv_bfloat16* bh, __nv_bfloat16* bl, int nb,
                     const float* __restrict__ c, __nv_bfloat16* ch, __nv_bfloat16* cl, int nc)
{
    int i = blockIdx.x * blockDim.x + threadIdx.x;
    if (i < na)               split1(a[i], ah, al, i);
    else if (i < na + nb)     split1(b[i - na], bh, bl, i - na);
    else if (i < na + nb + nc) split1(c[i - na - nb], ch, cl, i - na - nb);
}

/* ---------------- 4-way split-K reduce + fused hi/lo split ---------------- */
__global__ void red4_cvt(const float* __restrict__ p, float* __restrict__ o,
                         __nv_bfloat16* __restrict__ hi, __nv_bfloat16* __restrict__ lo,
                         int n)
{
    int i = blockIdx.x * blockDim.x + threadIdx.x;
    if (i >= n) return;
    float v = p[i] + p[i + (size_t)n] + p[i + 2 * (size_t)n] + p[i + 3 * (size_t)n];
    o[i] = v;
    split1(v, hi, lo, i);
}

/* ================= split-bf16 mma.sync GEMM =================
   2-stage cp.async pipeline, ONE __syncthreads per K-chunk.
   Order per chunk: WAIT0 (own groups <= kc done) -> __syncthreads (all
   threads' chunk-kc data visible; all warps past compute kc-1) -> issue
   loads for kc+1 -> compute kc.  cp.async groups are PER-THREAD: the
   barrier must sit between wait and consumption (R10 lesson). */
#define PITCH 40                   /* bf16 elems per smem row (80B, 16B-aligned) */
#define TILEB (128 * PITCH * 2)    /* 10240 bytes per tile */
#define STAGEB (4 * TILEB)         /* 40960: Ah, Al, Bh, Bl */
#define NSTAGE 2

template<int EPI>
__global__ void __launch_bounds__(256, 2)
tgemm(const __nv_bfloat16* __restrict__ Ah, const __nv_bfloat16* __restrict__ Al,
      const __nv_bfloat16* __restrict__ Bh, const __nv_bfloat16* __restrict__ Bl,
      float* __restrict__ C, int Nb, int nk,
      int lda, int ldb, int ldc, const float* __restrict__ bias,
      int zK, long long zC)
{
    extern __shared__ char smem[];
    const int tid  = threadIdx.x;
    const int lane = tid & 31, wid = tid >> 5;
    const int m0 = blockIdx.y * 128, n0 = blockIdx.x * 128;
    const int warp_m0 = (wid & 3) * 32, warp_n0 = (wid >> 2) * 64;
    const uint32_t sbase = smem_u32(smem);

    Ah += (size_t)blockIdx.z * zK;  Al += (size_t)blockIdx.z * zK;
    Bh += (size_t)blockIdx.z * zK;  Bl += (size_t)blockIdx.z * zK;
    C  += (size_t)blockIdx.z * zC;

    float acc[2][8][4];
#pragma unroll
    for (int i = 0; i < 2; i++)
#pragma unroll
        for (int j = 0; j < 8; j++)
#pragma unroll
            for (int k = 0; k < 4; k++) acc[i][j][k] = 0.f;

    auto load_stage = [&](int kc, int st) {
        const int k0 = kc * 32;
        const uint32_t sb = sbase + st * STAGEB;
        for (int i = tid; i < 512; i += 256) {
            int r = i >> 2, j = i & 3;
            uint32_t doff = r * (PITCH * 2) + j * 16;
            size_t ga = ((size_t)(m0 + r) * lda + k0) * 2 + j * 16;
            cp_async16(sb + doff,             (const char*)Ah + ga, 16);
            cp_async16(sb + TILEB + doff,     (const char*)Al + ga, 16);
            int nr = n0 + r;
            int ok = (nr < Nb) ? 16 : 0;
            int nrc = (nr < Nb) ? nr : (Nb - 1);
            size_t gb = ((size_t)nrc * ldb + k0) * 2 + j * 16;
            cp_async16(sb + 2 * TILEB + doff, (const char*)Bh + gb, ok);
            cp_async16(sb + 3 * TILEB + doff, (const char*)Bl + gb, ok);
        }
        CP_COMMIT();
    };

    /* prologue: stage 0 in flight */
    load_stage(0, 0);

    const int r8 = lane & 7, g = lane >> 3;

    for (int kc = 0; kc < nk; kc++) {
        CP_WAIT0();            /* own copies for chunk kc retired            */
        __syncthreads();       /* all threads' chunk-kc data visible; all
                                  warps finished compute kc-1                */
        if (kc + 1 < nk) load_stage(kc + 1, (kc + 1) & 1);

        const uint32_t sb = sbase + (kc & 1) * STAGEB;
#pragma unroll
        for (int ks = 0; ks < 32; ks += 16) {
            uint32_t ahf[2][4], alf[2][4];
#pragma unroll
            for (int mi = 0; mi < 2; mi++) {
                int row = warp_m0 + mi * 16 + r8 + ((g & 1) << 3);
                int col = ks + ((g >> 1) << 3);
                uint32_t a = sb + row * (PITCH * 2) + col * 2;
                LDSM_X4(ahf[mi], a);
                LDSM_X4(alf[mi], a + TILEB);
            }
#pragma unroll
            for (int nt = 0; nt < 4; nt++) {
                uint32_t bh[4], bl[4];
                {
                    int row = warp_n0 + nt * 16 + r8 + ((g >> 1) << 3);
                    int col = ks + ((g & 1) << 3);
                    uint32_t a = sb + 2 * TILEB + row * (PITCH * 2) + col * 2;
                    LDSM_X4(bh, a);
                    LDSM_X4(bl, a + TILEB);
                }
#pragma unroll
                for (int mi = 0; mi < 2; mi++)
#pragma unroll
                    for (int hf = 0; hf < 2; hf++)
                        mma16816(acc[mi][nt * 2 + hf], ahf[mi], bh[hf * 2], bh[hf * 2 + 1]);
#pragma unroll
                for (int mi = 0; mi < 2; mi++)
#pragma unroll
                    for (int hf = 0; hf < 2; hf++)
                        mma16816(acc[mi][nt * 2 + hf], ahf[mi], bl[hf * 2], bl[hf * 2 + 1]);
#pragma unroll
                for (int mi = 0; mi < 2; mi++)
#pragma unroll
                    for (int hf = 0; hf < 2; hf++)
                        mma16816(acc[mi][nt * 2 + hf], alf[mi], bh[hf * 2], bh[hf * 2 + 1]);
            }
        }
    }

    const int rb = lane >> 2, cp2 = (lane & 3) * 2;
#pragma unroll
    for (int mi = 0; mi < 2; mi++) {
        int rowa = m0 + warp_m0 + mi * 16 + rb;
#pragma unroll
        for (int nj = 0; nj < 8; nj++) {
            int col = n0 + warp_n0 + nj * 8 + cp2;
            if (col >= Nb) continue;
            float v0 = acc[mi][nj][0], v1 = acc[mi][nj][1];
            float v2 = acc[mi][nj][2], v3 = acc[mi][nj][3];
            if (EPI == 1) {
                float b0 = bias[col], b1 = bias[col + 1];
                v0 = softplusf(v0 + b0); v1 = softplusf(v1 + b1);
                v2 = softplusf(v2 + b0); v3 = softplusf(v3 + b1);
            }
            *(float2*)&C[(size_t)rowa * ldc + col]       = make_float2(v0, v1);
            *(float2*)&C[(size_t)(rowa + 8) * ldc + col] = make_float2(v2, v3);
        }
    }
}

/* ---------------- depthwise conv + SiLU + split: 4 t per thread ---------------- */
__global__ void conv_silu_kernel(const float* __restrict__ xz,
                                 const float* __restrict__ w,
                                 const float* __restrict__ bias,
                                 float* __restrict__ xc,
                                 __nv_bfloat16* __restrict__ xc_hi,
                                 __nv_bfloat16* __restrict__ xc_lo)
{
    int gidx = blockIdx.x * blockDim.x + threadIdx.x;
    if (gidx >= NTOK * D_INNER / 4) return;
    int d  = gidx % D_INNER;
    int tq = gidx / D_INNER;
    int b  = tq / (L_SEQ / 4);
    int t0 = (tq % (L_SEQ / 4)) * 4;

    const float* base = xz + (size_t)b * L_SEQ * (2 * D_INNER) + d;
    float v[7];
#pragma unroll
    for (int j = 0; j < 7; j++) {
        int ts = t0 - 3 + j;
        v[j] = (ts >= 0) ? base[(size_t)ts * (2 * D_INNER)] : 0.f;
    }
    float w0 = w[d * 4], w1 = w[d * 4 + 1], w2 = w[d * 4 + 2], w3 = w[d * 4 + 3];
    float bs = bias[d];
#pragma unroll
    for (int i = 0; i < 4; i++) {
        float s = bs + w0 * v[i] + w1 * v[i + 1] + w2 * v[i + 2] + w3 * v[i + 3];
        float sig = 1.f / (1.f + __expf(-s));
        float o = s * sig;
        size_t oi = ((size_t)(b * L_SEQ + t0 + i)) * D_INNER + d;
        xc[oi] = o;
        split1(o, xc_hi, xc_lo, oi);
    }
}

/* ================= chunk-parallel selective scan ================= */
#define NCH 16
#define CHL (L_SEQ / NCH)   /* 128 */
#define ST(dl, c, k) (((dl) * (NCH + 1) + (c)) * 17 + (k))

__device__ __forceinline__ void ladder16(float e1, float* p) {
    p[0]  = e1;          p[1]  = e1 * e1;
    p[2]  = p[1] * e1;   p[3]  = p[1] * p[1];
    p[4]  = p[3] * e1;   p[5]  = p[3] * p[1];
    p[6]  = p[3] * p[2]; p[7]  = p[3] * p[3];
    p[8]  = p[7] * p[0]; p[9]  = p[7] * p[1];
    p[10] = p[7] * p[2]; p[11] = p[7] * p[3];
    p[12] = p[7] * p[4]; p[13] = p[7] * p[5];
    p[14] = p[7] * p[6]; p[15] = p[7] * p[7];
}

__global__ __launch_bounds__(512)
void scan2_kernel(const float* __restrict__ xc, const float* __restrict__ dt,
                  const float* __restrict__ xp, const float* __restrict__ xz,
                  const float* __restrict__ A_log, const float* __restrict__ Dp,
                  __nv_bfloat16* __restrict__ y_hi, __nv_bfloat16* __restrict__ y_lo)
{
    __shared__ float ssc[32 * (NCH + 1) * 17];

    const int lane = threadIdx.x & 31;
    const int wch  = threadIdx.x >> 5;
    const int gd   = blockIdx.x * 32 + lane;
    const int b    = gd >> 11;
    const int d    = gd & (D_INNER - 1);

    float Av[D_STATE];
    bool fast = true;
#pragma unroll
    for (int n = 0; n < D_STATE; n++) {
        Av[n] = -expf(A_log[d * D_STATE + n]);
        fast = fast && (fabsf(Av[n] + (float)(n + 1)) < 2e-5f * (float)(n + 1));
    }
    const float Dv = Dp[d];
    const size_t rowbase = (size_t)b * L_SEQ + wch * CHL;

    float h[D_STATE];
#pragma unroll
    for (int n = 0; n < D_STATE; n++) h[n] = 0.f;
    float S = 0.f;

    for (int s = 0; s < CHL; s++) {
        size_t row = rowbase + s;
        float dtv = dt[row * D_INNER + d];
        float xv  = xc[row * D_INNER + d];
        const float* xr = xp + row * XPROJ + DT_RANK;
        float4 B0 = *(const float4*)(xr + 0), B1 = *(const float4*)(xr + 4);
        float4 B2 = *(const float4*)(xr + 8), B3 = *(const float4*)(xr + 12);
        float Bv[16] = {B0.x, B0.y, B0.z, B0.w, B1.x, B1.y, B1.z, B1.w,
                        B2.x, B2.y, B2.z, B2.w, B3.x, B3.y, B3.z, B3.w};
        S += dtv;
        float du = dtv * xv;
        float p[16];
        if (fast) {
            ladder16(__expf(-dtv), p);
        } else {
#pragma unroll
            for (int n = 0; n < D_STATE; n++) p[n] = __expf(dtv * Av[n]);
        }
#pragma unroll
        for (int n = 0; n < D_STATE; n++) h[n] = p[n] * h[n] + du * Bv[n];
    }

#pragma unroll
    for (int n = 0; n < D_STATE; n++) ssc[ST(lane, wch, n)] = h[n];
    ssc[ST(lane, wch, 16)] = S;
    __syncthreads();

    {
        int dr = 2 * wch + (lane >> 4);
        int c  = lane & 15;
        int d2 = (blockIdx.x * 32 + dr) & (D_INNER - 1);

        float Av2[D_STATE];
        bool fast2 = true;
#pragma unroll
        for (int n = 0; n < D_STATE; n++) {
            Av2[n] = -expf(A_log[d2 * D_STATE + n]);
            fast2 = fast2 && (fabsf(Av2[n] + (float)(n + 1)) < 2e-5f * (float)(n + 1));
        }

        float Sc = ssc[ST(dr, c, 16)];
        float bb[16];
#pragma unroll
        for (int n = 0; n < D_STATE; n++) bb[n] = ssc[ST(dr, c, n)];

#pragma unroll
        for (int off = 1; off < NCH; off <<= 1) {
            float Sj = __shfl_up_sync(0xffffffffu, Sc, off, 16);
            float bj[16];
#pragma unroll
            for (int n = 0; n < D_STATE; n++)
                bj[n] = __shfl_up_sync(0xffffffffu, bb[n], off, 16);
            float p[16];
            if (fast2) ladder16(__expf(-Sc), p);
            else {
#pragma unroll
                for (int n = 0; n < D_STATE; n++) p[n] = __expf(Av2[n] * Sc);
            }
            if (c >= off) {
#pragma unroll
                for (int n = 0; n < D_STATE; n++) bb[n] = p[n] * bj[n] + bb[n];
                Sc += Sj;
            }
        }
#pragma unroll
        for (int n = 0; n < D_STATE; n++) {
            float t = __shfl_up_sync(0xffffffffu, bb[n], 1, 16);
            ssc[ST(dr, c, n)] = (c == 0) ? 0.f : t;
        }
    }
    __syncthreads();

#pragma unroll
    for (int n = 0; n < D_STATE; n++) h[n] = ssc[ST(lane, wch, n)];

    for (int s = 0; s < CHL; s++) {
        size_t row = rowbase + s;
        float dtv = dt[row * D_INNER + d];
        float xv  = xc[row * D_INNER + d];
        float zv  = xz[row * (2 * D_INNER) + D_INNER + d];
        const float* xr = xp + row * XPROJ + DT_RANK;
        float4 B0 = *(const float4*)(xr + 0),  B1 = *(const float4*)(xr + 4);
        float4 B2 = *(const float4*)(xr + 8),  B3 = *(const float4*)(xr + 12);
        float4 C0 = *(const float4*)(xr + 16), C1 = *(const float4*)(xr + 20);
        float4 C2 = *(const float4*)(xr + 24), C3 = *(const float4*)(xr + 28);
        float Bv[16] = {B0.x, B0.y, B0.z, B0.w, B1.x, B1.y, B1.z, B1.w,
                        B2.x, B2.y, B2.z, B2.w, B3.x, B3.y, B3.z, B3.w};
        float Cv[16] = {C0.x, C0.y, C0.z, C0.w, C1.x, C1.y, C1.z, C1.w,
                        C2.x, C2.y, C2.z, C2.w, C3.x, C3.y, C3.z, C3.w};
        float du = dtv * xv;
        float p[16];
        if (fast) {
            ladder16(__expf(-dtv), p);
        } else {
#pragma unroll
            for (int n = 0; n < D_STATE; n++) p[n] = __expf(dtv * Av[n]);
        }
        float yv = 0.f;
#pragma unroll
        for (int n = 0; n < D_STATE; n++) {
            h[n] = p[n] * h[n] + du * Bv[n];
            yv  += h[n] * Cv[n];
        }
        float sig = 1.f / (1.f + __expf(-zv));
        float yo = (yv + xv * Dv) * (zv * sig);
        split1(yo, y_hi, y_lo, row * D_INNER + d);
    }
}

/* ---------------- launch ---------------- */
extern "C" void kernel_launch(void* const* d_in, const int* in_sizes, int n_in,
                              void* d_out, int out_size)
{
    const float* x      = (const float*)d_in[0];
    const float* W_in   = (const float*)d_in[1];
    const float* conv_w = (const float*)d_in[2];
    const float* conv_b = (const float*)d_in[3];
    const float* W_xprj = (const float*)d_in[4];
    const float* W_dt   = (const float*)d_in[5];
    const float* b_dt   = (const float*)d_in[6];
    const float* A_log  = (const float*)d_in[7];
    const float* Dp     = (const float*)d_in[8];
    const float* W_out  = (const float*)d_in[9];
    float* out = (float*)d_out;

    float *xz, *xc, *xp, *xpp, *dtb;
    __nv_bfloat16 *xh, *xl, *wih, *wil, *wxh, *wxl, *wdh, *wdl, *woh, *wol;
    __nv_bfloat16 *xch, *xcl, *xph, *xpl, *yh, *yl;
    cudaGetSymbolAddress((void**)&xz,  g_xz);
    cudaGetSymbolAddress((void**)&xc,  g_xc);
    cudaGetSymbolAddress((void**)&xp,  g_xp);
    cudaGetSymbolAddress((void**)&xpp, g_xp_part);
    cudaGetSymbolAddress((void**)&dtb, g_dt);
    cudaGetSymbolAddress((void**)&xh,  g_x_hi);  cudaGetSymbolAddress((void**)&xl,  g_x_lo);
    cudaGetSymbolAddress((void**)&wih, g_wi_hi); cudaGetSymbolAddress((void**)&wil, g_wi_lo);
    cudaGetSymbolAddress((void**)&wxh, g_wx_hi); cudaGetSymbolAddress((void**)&wxl, g_wx_lo);
    cudaGetSymbolAddress((void**)&wdh, g_wd_hi); cudaGetSymbolAddress((void**)&wdl, g_wd_lo);
    cudaGetSymbolAddress((void**)&woh, g_wo_hi); cudaGetSymbolAddress((void**)&wol, g_wo_lo);
    cudaGetSymbolAddress((void**)&xch, g_xc_hi); cudaGetSymbolAddress((void**)&xcl, g_xc_lo);
    cudaGetSymbolAddress((void**)&xph, g_xp_hi); cudaGetSymbolAddress((void**)&xpl, g_xp_lo);
    cudaGetSymbolAddress((void**)&yh,  g_y_hi);  cudaGetSymbolAddress((void**)&yl,  g_y_lo);

    const int SMEM_BYTES = NSTAGE * STAGEB;  /* 81920 */
    cudaFuncSetAttribute(tgemm<0>, cudaFuncAttributeMaxDynamicSharedMemorySize, SMEM_BYTES);
    cudaFuncSetAttribute(tgemm<1>, cudaFuncAttributeMaxDynamicSharedMemorySize, SMEM_BYTES);

    /* 1-3. splits (ordered so launch #4 = big GEMM for the ncu window) */
    cvt_pair<<<(NTOK * D_MODEL + 255) / 256, 256>>>(x, xh, xl, NTOK * D_MODEL);
    cvt_pair<<<(2 * D_INNER * D_MODEL + 255) / 256, 256>>>(W_in, wih, wil, 2 * D_INNER * D_MODEL);
    {
        int na = XPROJ * D_INNER, nb = D_INNER * DT_RANK, nc = D_MODEL * D_INNER;
        cvt3<<<(na + nb + nc + 255) / 256, 256>>>(W_xprj, wxh, wxl, na,
                                                  W_dt, wdh, wdl, nb,
                                                  W_out, woh, wol, nc);
    }

    /* 4. xz = x @ W_in^T */
    tgemm<0><<<dim3(32, 32), 256, SMEM_BYTES>>>(xh, xl, wih, wil, xz,
                                                2 * D_INNER, D_MODEL / 32,
                                                D_MODEL, D_MODEL, 2 * D_INNER, nullptr,
                                                0, 0LL);

    /* 5. conv + silu + split */
    conv_silu_kernel<<<(NTOK * D_INNER / 4 + 255) / 256, 256>>>(xz, conv_w, conv_b, xc, xch, xcl);

    /* 6-7. xp = xc @ W_xproj^T (split-K x4) + reduce */
    tgemm<0><<<dim3(1, 32, 4), 256, SMEM_BYTES>>>(xch, xcl, wxh, wxl, xpp,
                                                  XPROJ, (D_INNER / 4) / 32,
                                                  D_INNER, D_INNER, XPROJ, nullptr,
                                                  D_INNER / 4, (long long)NTOK * XPROJ);
    red4_cvt<<<(NTOK * XPROJ + 255) / 256, 256>>>(xpp, xp, xph, xpl, NTOK * XPROJ);

    /* 8. dt = softplus(xp[:, :64] @ W_dt^T + b_dt) */
    tgemm<1><<<dim3(16, 32), 256, SMEM_BYTES>>>(xph, xpl, wdh, wdl, dtb,
                                                D_INNER, DT_RANK / 32,
                                                XPROJ, DT_RANK, D_INNER, b_dt,
                                                0, 0LL);

    /* 9. chunk-parallel scan + fused epilogue */
    scan2_kernel<<<B_SZ * D_INNER / 32, 512>>>(xc, dtb, xp, xz, A_log, Dp, yh, yl);

    /* 10. out = y @ W_out^T */
    tgemm<0><<<dim3(8, 32), 256, SMEM_BYTES>>>(yh, yl, woh, wol, out,
                                               D_MODEL, D_INNER / 32,
                                               D_INNER, D_INNER, D_MODEL, nullptr,
                                               0, 0LL);
}

// round 16
// speedup vs baseline: 1.4495x; 1.4495x over previous
#include <cuda_runtime.h>
#include <cuda_bf16.h>
#include <cstdint>
#include <math.h>

#define B_SZ    2
#define L_SEQ   2048
#define D_MODEL 1024
#define D_INNER 2048
#define D_STATE 16
#define DT_RANK 64
#define NTOK    (B_SZ * L_SEQ)            /* 4096 tokens */
#define XPROJ   (DT_RANK + 2 * D_STATE)   /* 96 */

/* ================= scratch (no allocations allowed) ================= */
__device__ float g_xz[(size_t)NTOK * (2 * D_INNER)];
__device__ float g_xc[(size_t)NTOK * D_INNER];
__device__ float g_xp[(size_t)NTOK * XPROJ];
__device__ float g_xp_part[(size_t)8 * NTOK * XPROJ];
__device__ float g_out_part[(size_t)4 * NTOK * D_MODEL];
__device__ float g_dt[(size_t)NTOK * D_INNER];

__device__ __nv_bfloat16 g_x_hi [(size_t)NTOK * D_MODEL];
__device__ __nv_bfloat16 g_x_lo [(size_t)NTOK * D_MODEL];
__device__ __nv_bfloat16 g_wi_hi[(size_t)(2 * D_INNER) * D_MODEL];
__device__ __nv_bfloat16 g_wi_lo[(size_t)(2 * D_INNER) * D_MODEL];
__device__ __nv_bfloat16 g_wx_hi[(size_t)XPROJ * D_INNER];
__device__ __nv_bfloat16 g_wx_lo[(size_t)XPROJ * D_INNER];
__device__ __nv_bfloat16 g_wd_hi[(size_t)D_INNER * DT_RANK];
__device__ __nv_bfloat16 g_wd_lo[(size_t)D_INNER * DT_RANK];
__device__ __nv_bfloat16 g_wo_hi[(size_t)D_MODEL * D_INNER];
__device__ __nv_bfloat16 g_wo_lo[(size_t)D_MODEL * D_INNER];
__device__ __nv_bfloat16 g_xc_hi[(size_t)NTOK * D_INNER];
__device__ __nv_bfloat16 g_xc_lo[(size_t)NTOK * D_INNER];
__device__ __nv_bfloat16 g_xp_hi[(size_t)NTOK * XPROJ];
__device__ __nv_bfloat16 g_xp_lo[(size_t)NTOK * XPROJ];
__device__ __nv_bfloat16 g_y_hi [(size_t)NTOK * D_INNER];
__device__ __nv_bfloat16 g_y_lo [(size_t)NTOK * D_INNER];

__device__ __forceinline__ float softplusf(float x) {
    return fmaxf(x, 0.f) + log1pf(__expf(-fabsf(x)));
}
__device__ __forceinline__ uint32_t smem_u32(const void* p) {
    uint32_t a;
    asm("{ .reg .u64 t; cvta.to.shared.u64 t, %1; cvt.u32.u64 %0, t; }" : "=r"(a) : "l"(p));
    return a;
}
__device__ __forceinline__ void cp_async16(uint32_t dst, const void* src, int src_bytes) {
    asm volatile("cp.async.cg.shared.global [%0], [%1], 16, %2;"
                 :: "r"(dst), "l"(src), "r"(src_bytes) : "memory");
}
#define CP_COMMIT() asm volatile("cp.async.commit_group;" ::: "memory")
#define CP_WAIT1()  asm volatile("cp.async.wait_group 1;" ::: "memory")
#define CP_WAIT0()  asm volatile("cp.async.wait_group 0;" ::: "memory")
#define LDSM_X4(d, a) \
    asm volatile("ldmatrix.sync.aligned.m8n8.x4.shared.b16 {%0,%1,%2,%3}, [%4];" \
                 : "=r"((d)[0]), "=r"((d)[1]), "=r"((d)[2]), "=r"((d)[3]) : "r"(a))
__device__ __forceinline__ void mma16816(float* c, const uint32_t* a, uint32_t b0, uint32_t b1) {
    asm volatile("mma.sync.aligned.m16n8k16.row.col.f32.bf16.bf16.f32 "
                 "{%0,%1,%2,%3}, {%4,%5,%6,%7}, {%8,%9}, {%0,%1,%2,%3};"
                 : "+f"(c[0]), "+f"(c[1]), "+f"(c[2]), "+f"(c[3])
                 : "r"(a[0]), "r"(a[1]), "r"(a[2]), "r"(a[3]), "r"(b0), "r"(b1));
}

/* ---------------- fp32 -> (hi, lo) bf16 split ---------------- */
__device__ __forceinline__ void split1(float v, __nv_bfloat16* hi, __nv_bfloat16* lo, size_t i) {
    __nv_bfloat16 h = __float2bfloat16(v);
    hi[i] = h;
    lo[i] = __float2bfloat16(v - __bfloat162float(h));
}

__global__ void cvt_pair(const float* __restrict__ s, __nv_bfloat16* __restrict__ hi,
                         __nv_bfloat16* __restrict__ lo, int n)
{
    int i = blockIdx.x * blockDim.x + threadIdx.x;
    if (i >= n) return;
    split1(s[i], hi, lo, i);
}

/* merged cvt for three arrays */
__global__ void cvt3(const float* __restrict__ a, __nv_bfloat16* ah, __nv_bfloat16* al, int na,
                     const float* __restrict__ b, __nv_bfloat16* bh, __nv_bfloat16* bl, int nb,
                     const float* __restrict__ c, __nv_bfloat16* ch, __nv_bfloat16* cl, int nc)
{
    int i = blockIdx.x * blockDim.x + threadIdx.x;
    if (i < na)               split1(a[i], ah, al, i);
    else if (i < na + nb)     split1(b[i - na], bh, bl, i - na);
    else if (i < na + nb + nc) split1(c[i - na - nb], ch, cl, i - na - nb);
}

/* ---------------- 8-way split-K reduce + fused hi/lo split ---------------- */
__global__ void red8_cvt(const float* __restrict__ p, float* __restrict__ o,
                         __nv_bfloat16* __restrict__ hi, __nv_bfloat16* __restrict__ lo,
                         int n)
{
    int i = blockIdx.x * blockDim.x + threadIdx.x;
    if (i >= n) return;
    float v = 0.f;
#pragma unroll
    for (int z = 0; z < 8; z++) v += p[i + (size_t)z * n];
    o[i] = v;
    split1(v, hi, lo, i);
}

/* ---------------- 4-way split-K reduce, plain fp32 output ---------------- */
__global__ void red4_out(const float* __restrict__ p, float* __restrict__ o, int n)
{
    int i = blockIdx.x * blockDim.x + threadIdx.x;
    if (i >= n) return;
    o[i] = p[i] + p[i + (size_t)n] + p[i + 2 * (size_t)n] + p[i + 3 * (size_t)n];
}

/* ================= split-bf16 mma.sync GEMM =================
   Proven R6 loop: load(kc+1) -> commit -> WAIT1 -> sync -> compute -> sync.
   (wait precedes the barrier; barrier makes every thread's copies visible —
   cp.async groups are per-thread. End sync protects buffer reuse.) */
#define PITCH 40                   /* bf16 elems per smem row (80B, 16B-aligned) */
#define TILEB (128 * PITCH * 2)    /* 10240 bytes per tile */
#define STAGEB (4 * TILEB)         /* 40960: Ah, Al, Bh, Bl */
#define NSTAGE 2

template<int EPI>
__global__ void __launch_bounds__(256, 2)
tgemm(const __nv_bfloat16* __restrict__ Ah, const __nv_bfloat16* __restrict__ Al,
      const __nv_bfloat16* __restrict__ Bh, const __nv_bfloat16* __restrict__ Bl,
      float* __restrict__ C, int Nb, int nk,
      int lda, int ldb, int ldc, const float* __restrict__ bias,
      int zK, long long zC)
{
    extern __shared__ char smem[];
    const int tid  = threadIdx.x;
    const int lane = tid & 31, wid = tid >> 5;
    const int m0 = blockIdx.y * 128, n0 = blockIdx.x * 128;
    const int warp_m0 = (wid & 3) * 32, warp_n0 = (wid >> 2) * 64;
    const uint32_t sbase = smem_u32(smem);

    Ah += (size_t)blockIdx.z * zK;  Al += (size_t)blockIdx.z * zK;
    Bh += (size_t)blockIdx.z * zK;  Bl += (size_t)blockIdx.z * zK;
    C  += (size_t)blockIdx.z * zC;

    float acc[2][8][4];
#pragma unroll
    for (int i = 0; i < 2; i++)
#pragma unroll
        for (int j = 0; j < 8; j++)
#pragma unroll
            for (int k = 0; k < 4; k++) acc[i][j][k] = 0.f;

    auto load_stage = [&](int kc, int st) {
        const int k0 = kc * 32;
        const uint32_t sb = sbase + st * STAGEB;
        for (int i = tid; i < 512; i += 256) {
            int r = i >> 2, j = i & 3;
            uint32_t doff = r * (PITCH * 2) + j * 16;
            size_t ga = ((size_t)(m0 + r) * lda + k0) * 2 + j * 16;
            cp_async16(sb + doff,             (const char*)Ah + ga, 16);
            cp_async16(sb + TILEB + doff,     (const char*)Al + ga, 16);
            int nr = n0 + r;
            int ok = (nr < Nb) ? 16 : 0;
            int nrc = (nr < Nb) ? nr : (Nb - 1);
            size_t gb = ((size_t)nrc * ldb + k0) * 2 + j * 16;
            cp_async16(sb + 2 * TILEB + doff, (const char*)Bh + gb, ok);
            cp_async16(sb + 3 * TILEB + doff, (const char*)Bl + gb, ok);
        }
        CP_COMMIT();
    };

    load_stage(0, 0);

    const int r8 = lane & 7, g = lane >> 3;

    for (int kc = 0; kc < nk; kc++) {
        if (kc + 1 < nk) { load_stage(kc + 1, (kc + 1) & 1); CP_WAIT1(); }
        else             { CP_WAIT0(); }
        __syncthreads();

        const uint32_t sb = sbase + (kc & 1) * STAGEB;
#pragma unroll
        for (int ks = 0; ks < 32; ks += 16) {
            uint32_t ahf[2][4], alf[2][4];
#pragma unroll
            for (int mi = 0; mi < 2; mi++) {
                int row = warp_m0 + mi * 16 + r8 + ((g & 1) << 3);
                int col = ks + ((g >> 1) << 3);
                uint32_t a = sb + row * (PITCH * 2) + col * 2;
                LDSM_X4(ahf[mi], a);
                LDSM_X4(alf[mi], a + TILEB);
            }
#pragma unroll
            for (int nt = 0; nt < 4; nt++) {
                uint32_t bh[4], bl[4];
                {
                    int row = warp_n0 + nt * 16 + r8 + ((g >> 1) << 3);
                    int col = ks + ((g & 1) << 3);
                    uint32_t a = sb + 2 * TILEB + row * (PITCH * 2) + col * 2;
                    LDSM_X4(bh, a);
                    LDSM_X4(bl, a + TILEB);
                }
#pragma unroll
                for (int mi = 0; mi < 2; mi++)
#pragma unroll
                    for (int hf = 0; hf < 2; hf++)
                        mma16816(acc[mi][nt * 2 + hf], ahf[mi], bh[hf * 2], bh[hf * 2 + 1]);
#pragma unroll
                for (int mi = 0; mi < 2; mi++)
#pragma unroll
                    for (int hf = 0; hf < 2; hf++)
                        mma16816(acc[mi][nt * 2 + hf], ahf[mi], bl[hf * 2], bl[hf * 2 + 1]);
#pragma unroll
                for (int mi = 0; mi < 2; mi++)
#pragma unroll
                    for (int hf = 0; hf < 2; hf++)
                        mma16816(acc[mi][nt * 2 + hf], alf[mi], bh[hf * 2], bh[hf * 2 + 1]);
            }
        }
        __syncthreads();
    }

    const int rb = lane >> 2, cp2 = (lane & 3) * 2;
#pragma unroll
    for (int mi = 0; mi < 2; mi++) {
        int rowa = m0 + warp_m0 + mi * 16 + rb;
#pragma unroll
        for (int nj = 0; nj < 8; nj++) {
            int col = n0 + warp_n0 + nj * 8 + cp2;
            if (col >= Nb) continue;
            float v0 = acc[mi][nj][0], v1 = acc[mi][nj][1];
            float v2 = acc[mi][nj][2], v3 = acc[mi][nj][3];
            if (EPI == 1) {
                float b0 = bias[col], b1 = bias[col + 1];
                v0 = softplusf(v0 + b0); v1 = softplusf(v1 + b1);
                v2 = softplusf(v2 + b0); v3 = softplusf(v3 + b1);
            }
            *(float2*)&C[(size_t)rowa * ldc + col]       = make_float2(v0, v1);
            *(float2*)&C[(size_t)(rowa + 8) * ldc + col] = make_float2(v2, v3);
        }
    }
}

/* ---------------- depthwise conv + SiLU + split: 4 t per thread ---------------- */
__global__ void conv_silu_kernel(const float* __restrict__ xz,
                                 const float* __restrict__ w,
                                 const float* __restrict__ bias,
                                 float* __restrict__ xc,
                                 __nv_bfloat16* __restrict__ xc_hi,
                                 __nv_bfloat16* __restrict__ xc_lo)
{
    int gidx = blockIdx.x * blockDim.x + threadIdx.x;
    if (gidx >= NTOK * D_INNER / 4) return;
    int d  = gidx % D_INNER;
    int tq = gidx / D_INNER;
    int b  = tq / (L_SEQ / 4);
    int t0 = (tq % (L_SEQ / 4)) * 4;

    const float* base = xz + (size_t)b * L_SEQ * (2 * D_INNER) + d;
    float v[7];
#pragma unroll
    for (int j = 0; j < 7; j++) {
        int ts = t0 - 3 + j;
        v[j] = (ts >= 0) ? base[(size_t)ts * (2 * D_INNER)] : 0.f;
    }
    float w0 = w[d * 4], w1 = w[d * 4 + 1], w2 = w[d * 4 + 2], w3 = w[d * 4 + 3];
    float bs = bias[d];
#pragma unroll
    for (int i = 0; i < 4; i++) {
        float s = bs + w0 * v[i] + w1 * v[i + 1] + w2 * v[i + 2] + w3 * v[i + 3];
        float sig = 1.f / (1.f + __expf(-s));
        float o = s * sig;
        size_t oi = ((size_t)(b * L_SEQ + t0 + i)) * D_INNER + d;
        xc[oi] = o;
        split1(o, xc_hi, xc_lo, oi);
    }
}

/* ================= chunk-parallel selective scan ================= */
#define NCH 16
#define CHL (L_SEQ / NCH)   /* 128 */
#define ST(dl, c, k) (((dl) * (NCH + 1) + (c)) * 17 + (k))

__device__ __forceinline__ void ladder16(float e1, float* p) {
    p[0]  = e1;          p[1]  = e1 * e1;
    p[2]  = p[1] * e1;   p[3]  = p[1] * p[1];
    p[4]  = p[3] * e1;   p[5]  = p[3] * p[1];
    p[6]  = p[3] * p[2]; p[7]  = p[3] * p[3];
    p[8]  = p[7] * p[0]; p[9]  = p[7] * p[1];
    p[10] = p[7] * p[2]; p[11] = p[7] * p[3];
    p[12] = p[7] * p[4]; p[13] = p[7] * p[5];
    p[14] = p[7] * p[6]; p[15] = p[7] * p[7];
}

__global__ __launch_bounds__(512)
void scan2_kernel(const float* __restrict__ xc, const float* __restrict__ dt,
                  const float* __restrict__ xp, const float* __restrict__ xz,
                  const float* __restrict__ A_log, const float* __restrict__ Dp,
                  __nv_bfloat16* __restrict__ y_hi, __nv_bfloat16* __restrict__ y_lo)
{
    __shared__ float ssc[32 * (NCH + 1) * 17];

    const int lane = threadIdx.x & 31;
    const int wch  = threadIdx.x >> 5;
    const int gd   = blockIdx.x * 32 + lane;
    const int b    = gd >> 11;
    const int d    = gd & (D_INNER - 1);

    float Av[D_STATE];
    bool fast = true;
#pragma unroll
    for (int n = 0; n < D_STATE; n++) {
        Av[n] = -expf(A_log[d * D_STATE + n]);
        fast = fast && (fabsf(Av[n] + (float)(n + 1)) < 2e-5f * (float)(n + 1));
    }
    const float Dv = Dp[d];
    const size_t rowbase = (size_t)b * L_SEQ + wch * CHL;

    float h[D_STATE];
#pragma unroll
    for (int n = 0; n < D_STATE; n++) h[n] = 0.f;
    float S = 0.f;

    for (int s = 0; s < CHL; s++) {
        size_t row = rowbase + s;
        float dtv = dt[row * D_INNER + d];
        float xv  = xc[row * D_INNER + d];
        const float* xr = xp + row * XPROJ + DT_RANK;
        float4 B0 = *(const float4*)(xr + 0), B1 = *(const float4*)(xr + 4);
        float4 B2 = *(const float4*)(xr + 8), B3 = *(const float4*)(xr + 12);
        float Bv[16] = {B0.x, B0.y, B0.z, B0.w, B1.x, B1.y, B1.z, B1.w,
                        B2.x, B2.y, B2.z, B2.w, B3.x, B3.y, B3.z, B3.w};
        S += dtv;
        float du = dtv * xv;
        float p[16];
        if (fast) {
            ladder16(__expf(-dtv), p);
        } else {
#pragma unroll
            for (int n = 0; n < D_STATE; n++) p[n] = __expf(dtv * Av[n]);
        }
#pragma unroll
        for (int n = 0; n < D_STATE; n++) h[n] = p[n] * h[n] + du * Bv[n];
    }

#pragma unroll
    for (int n = 0; n < D_STATE; n++) ssc[ST(lane, wch, n)] = h[n];
    ssc[ST(lane, wch, 16)] = S;
    __syncthreads();

    {
        int dr = 2 * wch + (lane >> 4);
        int c  = lane & 15;
        int d2 = (blockIdx.x * 32 + dr) & (D_INNER - 1);

        float Av2[D_STATE];
        bool fast2 = true;
#pragma unroll
        for (int n = 0; n < D_STATE; n++) {
            Av2[n] = -expf(A_log[d2 * D_STATE + n]);
            fast2 = fast2 && (fabsf(Av2[n] + (float)(n + 1)) < 2e-5f * (float)(n + 1));
        }

        float Sc = ssc[ST(dr, c, 16)];
        float bb[16];
#pragma unroll
        for (int n = 0; n < D_STATE; n++) bb[n] = ssc[ST(dr, c, n)];

#pragma unroll
        for (int off = 1; off < NCH; off <<= 1) {
            float Sj = __shfl_up_sync(0xffffffffu, Sc, off, 16);
            float bj[16];
#pragma unroll
            for (int n = 0; n < D_STATE; n++)
                bj[n] = __shfl_up_sync(0xffffffffu, bb[n], off, 16);
            float p[16];
            if (fast2) ladder16(__expf(-Sc), p);
            else {
#pragma unroll
                for (int n = 0; n < D_STATE; n++) p[n] = __expf(Av2[n] * Sc);
            }
            if (c >= off) {
#pragma unroll
                for (int n = 0; n < D_STATE; n++) bb[n] = p[n] * bj[n] + bb[n];
                Sc += Sj;
            }
        }
#pragma unroll
        for (int n = 0; n < D_STATE; n++) {
            float t = __shfl_up_sync(0xffffffffu, bb[n], 1, 16);
            ssc[ST(dr, c, n)] = (c == 0) ? 0.f : t;
        }
    }
    __syncthreads();

#pragma unroll
    for (int n = 0; n < D_STATE; n++) h[n] = ssc[ST(lane, wch, n)];

    for (int s = 0; s < CHL; s++) {
        size_t row = rowbase + s;
        float dtv = dt[row * D_INNER + d];
        float xv  = xc[row * D_INNER + d];
        float zv  = xz[row * (2 * D_INNER) + D_INNER + d];
        const float* xr = xp + row * XPROJ + DT_RANK;
        float4 B0 = *(const float4*)(xr + 0),  B1 = *(const float4*)(xr + 4);
        float4 B2 = *(const float4*)(xr + 8),  B3 = *(const float4*)(xr + 12);
        float4 C0 = *(const float4*)(xr + 16), C1 = *(const float4*)(xr + 20);
        float4 C2 = *(const float4*)(xr + 24), C3 = *(const float4*)(xr + 28);
        float Bv[16] = {B0.x, B0.y, B0.z, B0.w, B1.x, B1.y, B1.z, B1.w,
                        B2.x, B2.y, B2.z, B2.w, B3.x, B3.y, B3.z, B3.w};
        float Cv[16] = {C0.x, C0.y, C0.z, C0.w, C1.x, C1.y, C1.z, C1.w,
                        C2.x, C2.y, C2.z, C2.w, C3.x, C3.y, C3.z, C3.w};
        float du = dtv * xv;
        float p[16];
        if (fast) {
            ladder16(__expf(-dtv), p);
        } else {
#pragma unroll
            for (int n = 0; n < D_STATE; n++) p[n] = __expf(dtv * Av[n]);
        }
        float yv = 0.f;
#pragma unroll
        for (int n = 0; n < D_STATE; n++) {
            h[n] = p[n] * h[n] + du * Bv[n];
            yv  += h[n] * Cv[n];
        }
        float sig = 1.f / (1.f + __expf(-zv));
        float yo = (yv + xv * Dv) * (zv * sig);
        split1(yo, y_hi, y_lo, row * D_INNER + d);
    }
}

/* ---------------- launch ---------------- */
extern "C" void kernel_launch(void* const* d_in, const int* in_sizes, int n_in,
                              void* d_out, int out_size)
{
    const float* x      = (const float*)d_in[0];
    const float* W_in   = (const float*)d_in[1];
    const float* conv_w = (const float*)d_in[2];
    const float* conv_b = (const float*)d_in[3];
    const float* W_xprj = (const float*)d_in[4];
    const float* W_dt   = (const float*)d_in[5];
    const float* b_dt   = (const float*)d_in[6];
    const float* A_log  = (const float*)d_in[7];
    const float* Dp     = (const float*)d_in[8];
    const float* W_out  = (const float*)d_in[9];
    float* out = (float*)d_out;

    float *xz, *xc, *xp, *xpp, *outp, *dtb;
    __nv_bfloat16 *xh, *xl, *wih, *wil, *wxh, *wxl, *wdh, *wdl, *woh, *wol;
    __nv_bfloat16 *xch, *xcl, *xph, *xpl, *yh, *yl;
    cudaGetSymbolAddress((void**)&xz,   g_xz);
    cudaGetSymbolAddress((void**)&xc,   g_xc);
    cudaGetSymbolAddress((void**)&xp,   g_xp);
    cudaGetSymbolAddress((void**)&xpp,  g_xp_part);
    cudaGetSymbolAddress((void**)&outp, g_out_part);
    cudaGetSymbolAddress((void**)&dtb,  g_dt);
    cudaGetSymbolAddress((void**)&xh,  g_x_hi);  cudaGetSymbolAddress((void**)&xl,  g_x_lo);
    cudaGetSymbolAddress((void**)&wih, g_wi_hi); cudaGetSymbolAddress((void**)&wil, g_wi_lo);
    cudaGetSymbolAddress((void**)&wxh, g_wx_hi); cudaGetSymbolAddress((void**)&wxl, g_wx_lo);
    cudaGetSymbolAddress((void**)&wdh, g_wd_hi); cudaGetSymbolAddress((void**)&wdl, g_wd_lo);
    cudaGetSymbolAddress((void**)&woh, g_wo_hi); cudaGetSymbolAddress((void**)&wol, g_wo_lo);
    cudaGetSymbolAddress((void**)&xch, g_xc_hi); cudaGetSymbolAddress((void**)&xcl, g_xc_lo);
    cudaGetSymbolAddress((void**)&xph, g_xp_hi); cudaGetSymbolAddress((void**)&xpl, g_xp_lo);
    cudaGetSymbolAddress((void**)&yh,  g_y_hi);  cudaGetSymbolAddress((void**)&yl,  g_y_lo);

    const int SMEM_BYTES = NSTAGE * STAGEB;  /* 81920 */
    cudaFuncSetAttribute(tgemm<0>, cudaFuncAttributeMaxDynamicSharedMemorySize, SMEM_BYTES);
    cudaFuncSetAttribute(tgemm<1>, cudaFuncAttributeMaxDynamicSharedMemorySize, SMEM_BYTES);

    /* 1-3. splits (ordered so launch #4 = big GEMM for the ncu window) */
    cvt_pair<<<(NTOK * D_MODEL + 255) / 256, 256>>>(x, xh, xl, NTOK * D_MODEL);
    cvt_pair<<<(2 * D_INNER * D_MODEL + 255) / 256, 256>>>(W_in, wih, wil, 2 * D_INNER * D_MODEL);
    {
        int na = XPROJ * D_INNER, nb = D_INNER * DT_RANK, nc = D_MODEL * D_INNER;
        cvt3<<<(na + nb + nc + 255) / 256, 256>>>(W_xprj, wxh, wxl, na,
                                                  W_dt, wdh, wdl, nb,
                                                  W_out, woh, wol, nc);
    }

    /* 4. xz = x @ W_in^T  (1024 CTAs, 32 chunks) */
    tgemm<0><<<dim3(32, 32), 256, SMEM_BYTES>>>(xh, xl, wih, wil, xz,
                                                2 * D_INNER, D_MODEL / 32,
                                                D_MODEL, D_MODEL, 2 * D_INNER, nullptr,
                                                0, 0LL);

    /* 5. conv + silu + split */
    conv_silu_kernel<<<(NTOK * D_INNER / 4 + 255) / 256, 256>>>(xz, conv_w, conv_b, xc, xch, xcl);

    /* 6-7. xp = xc @ W_xproj^T (split-K x8: 256 CTAs x 8 chunks) + reduce */
    tgemm<0><<<dim3(1, 32, 8), 256, SMEM_BYTES>>>(xch, xcl, wxh, wxl, xpp,
                                                  XPROJ, (D_INNER / 8) / 32,
                                                  D_INNER, D_INNER, XPROJ, nullptr,
                                                  D_INNER / 8, (long long)NTOK * XPROJ);
    red8_cvt<<<(NTOK * XPROJ + 255) / 256, 256>>>(xpp, xp, xph, xpl, NTOK * XPROJ);

    /* 8. dt = softplus(xp[:, :64] @ W_dt^T + b_dt) */
    tgemm<1><<<dim3(16, 32), 256, SMEM_BYTES>>>(xph, xpl, wdh, wdl, dtb,
                                                D_INNER, DT_RANK / 32,
                                                XPROJ, DT_RANK, D_INNER, b_dt,
                                                0, 0LL);

    /* 9. chunk-parallel scan + fused epilogue */
    scan2_kernel<<<B_SZ * D_INNER / 32, 512>>>(xc, dtb, xp, xz, A_log, Dp, yh, yl);

    /* 10-11. out = y @ W_out^T (split-K x4: 1024 CTAs x 16 chunks) + reduce */
    tgemm<0><<<dim3(8, 32, 4), 256, SMEM_BYTES>>>(yh, yl, woh, wol, outp,
                                                  D_MODEL, (D_INNER / 4) / 32,
                                                  D_INNER, D_INNER, D_MODEL, nullptr,
                                                  D_INNER / 4, (long long)NTOK * D_MODEL);
    red4_out<<<(NTOK * D_MODEL + 255) / 256, 256>>>(outp, out, NTOK * D_MODEL);
}